// round 14
// baseline (speedup 1.0000x reference)
#include <cuda_runtime.h>
#include <cuda_fp16.h>
#include <math.h>
#include <stdint.h>

// Problem constants
#define B_  2
#define T_  2048
#define DM  2048
#define H_  32
#define DH  64
#define M_  (B_*T_)   // 4096

// ---------------------------------------------------------------------------
// Half scratch (device globals: allocation-free per harness rules)
// ---------------------------------------------------------------------------
__device__ __half g_ah[(size_t)M_*DM];                           // hidden hi
__device__ __half g_wqh[(size_t)DM*DM];                          // Wq hi
__device__ __half g_woh[(size_t)DM*DM];                          // Wo hi
__device__ __half g_qh[(size_t)B_*H_*T_*DH];                     // rope'd+scaled Q hi
__device__ __half g_kh[(size_t)B_*H_*T_*DH];                     // K hi [B,H,T,Dh]
__device__ __half g_vth[(size_t)B_*H_*T_*DH];                    // V^T hi [B,H,Dh,T]
__device__ __half g_oh[(size_t)M_*DM];                           // attention out hi
__device__ float g_cos[T_*(DH/2)];
__device__ float g_sin[T_*(DH/2)];

// ---------------------------------------------------------------------------
// helpers
// ---------------------------------------------------------------------------
__device__ __forceinline__ uint32_t pack_h2(float a, float b) {
    __half2 h = __floats2half2_rn(a, b);
    return *(uint32_t*)&h;
}
__device__ __forceinline__ void mma16816(float* d, const uint32_t* a, const uint32_t* b) {
    asm volatile(
        "mma.sync.aligned.m16n8k16.row.col.f32.f16.f16.f32 "
        "{%0,%1,%2,%3}, {%4,%5,%6,%7}, {%8,%9}, {%0,%1,%2,%3};"
        : "+f"(d[0]), "+f"(d[1]), "+f"(d[2]), "+f"(d[3])
        : "r"(a[0]), "r"(a[1]), "r"(a[2]), "r"(a[3]), "r"(b[0]), "r"(b[1]));
}
__device__ __forceinline__ void ldsm_x4(uint32_t* r, uint32_t addr) {
    asm volatile(
        "ldmatrix.sync.aligned.m8n8.x4.shared.b16 {%0,%1,%2,%3}, [%4];"
        : "=r"(r[0]), "=r"(r[1]), "=r"(r[2]), "=r"(r[3]) : "r"(addr));
}
__device__ __forceinline__ void cp_async16(uint32_t saddr, const void* gptr) {
    asm volatile("cp.async.cg.shared.global [%0], [%1], 16;"
                 :: "r"(saddr), "l"(gptr));
}
#define CP_COMMIT() asm volatile("cp.async.commit_group;" ::: "memory")
#define CP_WAIT0()  asm volatile("cp.async.wait_group 0;" ::: "memory")
#define CP_WAIT1()  asm volatile("cp.async.wait_group 1;" ::: "memory")

// ---------------------------------------------------------------------------
// RoPE table
// ---------------------------------------------------------------------------
__global__ void rope_table_kernel() {
    int idx = blockIdx.x * blockDim.x + threadIdx.x;
    if (idx >= T_ * (DH/2)) return;
    int t = idx >> 5;
    int i = idx & 31;
    double inv = pow(10000.0, -((double)(2 * i)) / 64.0);
    double ang = (double)t * inv;
    g_cos[idx] = (float)cos(ang);
    g_sin[idx] = (float)sin(ang);
}

// ---------------------------------------------------------------------------
// fp32 -> half hi prep, vectorized (float4 -> uint2).  WHICH: 0=hidden,1=Wq,2=Wo
// ---------------------------------------------------------------------------
template<int WHICH>
__global__ void split_f32_kernel(const float* __restrict__ in) {
    size_t i = (size_t)blockIdx.x * 256 + threadIdx.x;
    float4 v = ((const float4*)in)[i];
    uint2* hw = (uint2*)(WHICH == 0 ? g_ah : WHICH == 1 ? g_wqh : g_woh);
    hw[i] = make_uint2(pack_h2(v.x, v.y), pack_h2(v.z, v.w));
}

// ---------------------------------------------------------------------------
// K prep: [B,T,H,Dh] fp32 -> [B,H,T,Dh] half (hi only), float4 -> uint2.
// ---------------------------------------------------------------------------
__global__ void prep_k_kernel(const float* __restrict__ Kg) {
    uint32_t w = blockIdx.x * 256 + threadIdx.x;     // < B*H*T*16
    int dh4 = w & 15;
    int tok = (w >> 4) & (T_ - 1);
    int h   = (w >> 15) & (H_ - 1);
    int b   = (int)(w >> 20);
    float4 v = ((const float4*)Kg)[(((size_t)(b * T_ + tok)) * H_ + h) * 16 + dh4];
    ((uint2*)g_kh)[(((size_t)(b * H_ + h)) * T_ + tok) * 16 + dh4] =
        make_uint2(pack_h2(v.x, v.y), pack_h2(v.z, v.w));
}

// ---------------------------------------------------------------------------
// V prep: [B,T,H,Dh] fp32 -> transposed [B,H,Dh,T] half (hi only).
// ---------------------------------------------------------------------------
__global__ void prep_v_kernel(const float* __restrict__ Vg) {
    __shared__ float stg[64 * 65];
    const int tid = threadIdx.x;
    const int kt  = blockIdx.x, h = blockIdx.y, b = blockIdx.z;
    const float* src = Vg + ((size_t)(b * T_ + kt * 64) * H_ + h) * DH;

    #pragma unroll
    for (int i = 0; i < 4; i++) {
        int chunk = i * 256 + tid;            // 64 rows x 16 float4
        int r = chunk >> 4, c4 = chunk & 15;
        float4 v = *(const float4*)(src + (size_t)r * (H_ * DH) + c4 * 4);
        float* d = stg + r * 65 + c4 * 4;
        d[0] = v.x; d[1] = v.y; d[2] = v.z; d[3] = v.w;
    }
    __syncthreads();

    const int kp = tid & 31, dhg = tid >> 5;
    #pragma unroll
    for (int i = 0; i < 8; i++) {
        int dh = dhg * 8 + i;
        float v0 = stg[(2 * kp)     * 65 + dh];
        float v1 = stg[(2 * kp + 1) * 65 + dh];
        size_t idx = ((size_t)(b * H_ + h) * DH + dh) * (T_ / 2) + kt * 32 + kp;
        ((uint32_t*)g_vth)[idx] = pack_h2(v0, v1);
    }
}

// ---------------------------------------------------------------------------
// Pure-FP16 GEMM, 3-stage cp.async pipeline: C = A @ W^T (hi x hi).
// ---------------------------------------------------------------------------
#define GSTW 28
#define GT_W (128*GSTW)                 // 3584 words
#define G_STAGE_W (2*GT_W)              // 7168 words
#define G_STAGES 3
#define SMEM_G_BYTES (G_STAGES*G_STAGE_W*4)   // 86016 B

template<int MODE>
__global__ __launch_bounds__(256)
void gemm_h_kernel(float* __restrict__ C) {
    extern __shared__ uint32_t smw[];

    const uint4* Agh = (const uint4*)(MODE == 0 ? g_ah  : g_oh);
    const uint4* Bgh = (const uint4*)(MODE == 0 ? g_wqh : g_woh);

    const int tid   = threadIdx.x;
    const int wid   = tid >> 5;
    const int lane  = tid & 31;
    const int g     = lane >> 2;
    const int t     = lane & 3;
    const int warpR = wid >> 2;
    const int warpC = wid & 3;
    const int rowBase = blockIdx.y * 128;
    const int colBase = blockIdx.x * 128;

    const int q4 = lane >> 3;
    const int rr = lane & 7;
    const int arow = (q4 & 1) * 8 + rr;
    const int aoff = (q4 >> 1) * 4;
    const int brow = (q4 >> 1) * 8 + rr;
    const int boff = (q4 & 1) * 4;

    const uint32_t smemS = (uint32_t)__cvta_generic_to_shared(smw);

    const int lr2 = tid >> 2;   // 0..63
    const int lc2 = tid & 3;    // 0..3

    auto issue = [&](int st, int kt) {
        uint32_t base = smemS + (uint32_t)st * G_STAGE_W * 4;
        #pragma unroll
        for (int i = 0; i < 2; i++) {
            int r = lr2 + i * 64;
            uint32_t so = (uint32_t)(r * GSTW + lc2 * 4) * 4;
            size_t ai = ((size_t)(rowBase + r)) * 256 + kt * 4 + lc2;
            size_t bi = ((size_t)(colBase + r)) * 256 + kt * 4 + lc2;
            cp_async16(base + so,            Agh + ai);
            cp_async16(base + GT_W * 4 + so, Bgh + bi);
        }
    };

    float acc[4][4][4];
    #pragma unroll
    for (int mt = 0; mt < 4; mt++)
        #pragma unroll
        for (int nt = 0; nt < 4; nt++)
            #pragma unroll
            for (int i = 0; i < 4; i++) acc[mt][nt][i] = 0.f;

    issue(0, 0); CP_COMMIT();
    issue(1, 1); CP_COMMIT();

    int st = 0;
    for (int kt = 0; kt < 64; kt++) {
        if (kt + 1 < 64) CP_WAIT1(); else CP_WAIT0();
        __syncthreads();
        if (kt + 2 < 64) {
            int ns = st + 2; if (ns >= G_STAGES) ns -= G_STAGES;
            issue(ns, kt + 2);
            CP_COMMIT();
        }

        const uint32_t AhS = smemS + (uint32_t)st * G_STAGE_W * 4;
        const uint32_t BhS = AhS + GT_W * 4;

        #pragma unroll
        for (int ks = 0; ks < 2; ks++) {
            uint32_t ah[4][4], bh[2][4];
            #pragma unroll
            for (int mt = 0; mt < 4; mt++) {
                uint32_t ao = ((warpR * 64 + mt * 16 + arow) * GSTW + ks * 8 + aoff) * 4;
                ldsm_x4(ah[mt], AhS + ao);
            }
            #pragma unroll
            for (int p = 0; p < 2; p++) {
                uint32_t bo = ((warpC * 32 + p * 16 + brow) * GSTW + ks * 8 + boff) * 4;
                ldsm_x4(bh[p], BhS + bo);
            }
            #pragma unroll
            for (int mt = 0; mt < 4; mt++)
                #pragma unroll
                for (int nt = 0; nt < 4; nt++)
                    mma16816(acc[mt][nt], ah[mt], &bh[nt >> 1][(nt & 1) * 2]);
        }

        if (++st >= G_STAGES) st = 0;
    }

    #pragma unroll
    for (int mt = 0; mt < 4; mt++) {
        #pragma unroll
        for (int nt = 0; nt < 4; nt++) {
            int m0 = rowBase + warpR * 64 + mt * 16 + g;
            int n  = colBase + warpC * 32 + nt * 8 + 2 * t;
            if (MODE == 0) {
                int hh = n >> 6;
                int d  = n & 63;   // even
                #pragma unroll
                for (int half = 0; half < 2; half++) {
                    int m = m0 + half * 8;
                    float x1 = acc[mt][nt][half * 2];
                    float x2 = acc[mt][nt][half * 2 + 1];
                    int bb = m >> 11;
                    int tt = m & (T_ - 1);
                    float c = g_cos[tt * 32 + (d >> 1)];
                    float s = g_sin[tt * 32 + (d >> 1)];
                    float xr1 = (x1 * c - x2 * s) * 0.125f;
                    float xr2 = (x1 * s + x2 * c) * 0.125f;
                    size_t idx = ((size_t)(bb * H_ + hh) * T_ + tt) * 32 + (d >> 1);
                    ((uint32_t*)g_qh)[idx] = pack_h2(xr1, xr2);
                }
            } else {
                float2 v0 = make_float2(acc[mt][nt][0], acc[mt][nt][1]);
                float2 v1 = make_float2(acc[mt][nt][2], acc[mt][nt][3]);
                *(float2*)(C + (size_t)m0 * DM + n)       = v0;
                *(float2*)(C + (size_t)(m0 + 8) * DM + n) = v1;
            }
        }
    }
}

// ---------------------------------------------------------------------------
// FP16 flash attention: 1-pass S, 1-pass PV, 3-stage cp.async K/V pipeline.
// ---------------------------------------------------------------------------
#define ASTW 44
#define AT_W (64*ASTW)                  // 2816 words / buffer
#define A_STAGE_W (2*AT_W)              // K + V per stage
#define A_STAGES 3
#define SMEM_A_BYTES (A_STAGES*A_STAGE_W*4)   // 67584 B

__global__ __launch_bounds__(256)
void attn_mma_kernel() {
    extern __shared__ uint32_t smw[];

    const int tid  = threadIdx.x;
    const int wid  = tid >> 5;
    const int lane = tid & 31;
    const int g    = lane >> 2;
    const int t    = lane & 3;
    const int bx   = (int)gridDim.x - 1 - (int)blockIdx.x;   // heavy blocks first
    const int h    = blockIdx.y;
    const int b    = blockIdx.z;
    const int q0   = bx * 128;
    const int wbase = wid * 16;

    const int q4 = lane >> 3;
    const int rr = lane & 7;

    const uint32_t smemS = (uint32_t)__cvta_generic_to_shared(smw);

    // ---- Q A-frags direct from gmem (hi only) ----
    uint32_t qh[4][4];
    {
        const uint32_t* qhw = (const uint32_t*)g_qh
            + (((size_t)(b * H_ + h)) * T_ + q0 + wbase + g) * 32;
        #pragma unroll
        for (int s = 0; s < 4; s++) {
            int o = s * 8 + t;
            qh[s][0] = qhw[o];           qh[s][1] = qhw[8 * 32 + o];
            qh[s][2] = qhw[o + 4];       qh[s][3] = qhw[8 * 32 + o + 4];
        }
    }

    float m0 = -1e30f, m1 = -1e30f, l0 = 0.f, l1 = 0.f;
    float oacc[8][4];
    #pragma unroll
    for (int nt = 0; nt < 8; nt++)
        #pragma unroll
        for (int i = 0; i < 4; i++) oacc[nt][i] = 0.f;

    const int nkt = 2 * bx + 2;

    const uint4* kh4 = (const uint4*)g_kh  + ((size_t)(b * H_ + h) * T_) * 8;
    const uint4* vh4 = (const uint4*)g_vth + ((size_t)(b * H_ + h) * DH) * (T_ / 8);

    const int ldr = tid >> 3;   // 0..31 (row, +32)
    const int ldc = tid & 7;    // uint4 chunk

    auto issue = [&](int st, int kt) {
        uint32_t base = smemS + (uint32_t)st * A_STAGE_W * 4;
        #pragma unroll
        for (int i = 0; i < 2; i++) {
            int r = ldr + i * 32;
            uint32_t so = (uint32_t)(r * ASTW + ldc * 4) * 4;
            cp_async16(base + so,            kh4 + (size_t)(kt * 64 + r) * 8 + ldc);
            cp_async16(base + AT_W * 4 + so, vh4 + (size_t)r * 256 + kt * 8 + ldc);
        }
    };

    const int qw_min = q0 + wbase;
    const int qw_max = q0 + wbase + 15;

    issue(0, 0); CP_COMMIT();
    if (nkt > 1) { issue(1, 1); CP_COMMIT(); }

    int st = 0;
    for (int kt = 0; kt < nkt; kt++) {
        const int ktb = kt * 64;

        if (kt + 1 < nkt) CP_WAIT1(); else CP_WAIT0();
        __syncthreads();
        if (kt + 2 < nkt) {
            int ns = st + 2; if (ns >= A_STAGES) ns -= A_STAGES;
            issue(ns, kt + 2);
            CP_COMMIT();
        }

        const uint32_t KhS = smemS + (uint32_t)st * A_STAGE_W * 4;
        const uint32_t VhS = KhS + AT_W * 4;
        if (++st >= A_STAGES) st = 0;

        if (ktb > qw_max) continue;   // fully masked for this warp

        // ---- S = Q K^T (1-pass fp16) ----
        float sacc[8][4];
        #pragma unroll
        for (int nt = 0; nt < 8; nt++)
            #pragma unroll
            for (int i = 0; i < 4; i++) sacc[nt][i] = 0.f;

        #pragma unroll
        for (int nt = 0; nt < 8; nt++) {
            #pragma unroll
            for (int sp = 0; sp < 2; sp++) {
                uint32_t kb2[4];
                ldsm_x4(kb2, KhS + (((nt * 8 + rr) * ASTW) + sp * 16 + q4 * 4) * 4);
                mma16816(sacc[nt], qh[2 * sp],     &kb2[0]);
                mma16816(sacc[nt], qh[2 * sp + 1], &kb2[2]);
            }
        }

        // ---- causal mask (diagonal tiles only) ----
        if (ktb + 63 > qw_min) {
            int qr0 = qw_min + g, qr1 = qr0 + 8;
            #pragma unroll
            for (int nt = 0; nt < 8; nt++) {
                int kc0 = ktb + nt * 8 + 2 * t;
                if (kc0     > qr0) sacc[nt][0] = -1e30f;
                if (kc0 + 1 > qr0) sacc[nt][1] = -1e30f;
                if (kc0     > qr1) sacc[nt][2] = -1e30f;
                if (kc0 + 1 > qr1) sacc[nt][3] = -1e30f;
            }
        }

        // ---- online softmax ----
        float mx0 = -1e30f, mx1 = -1e30f;
        #pragma unroll
        for (int nt = 0; nt < 8; nt++) {
            mx0 = fmaxf(mx0, fmaxf(sacc[nt][0], sacc[nt][1]));
            mx1 = fmaxf(mx1, fmaxf(sacc[nt][2], sacc[nt][3]));
        }
        mx0 = fmaxf(mx0, __shfl_xor_sync(0xffffffffu, mx0, 1));
        mx0 = fmaxf(mx0, __shfl_xor_sync(0xffffffffu, mx0, 2));
        mx1 = fmaxf(mx1, __shfl_xor_sync(0xffffffffu, mx1, 1));
        mx1 = fmaxf(mx1, __shfl_xor_sync(0xffffffffu, mx1, 2));

        float mn0 = fmaxf(m0, mx0), mn1 = fmaxf(m1, mx1);
        float c0 = __expf(m0 - mn0), c1 = __expf(m1 - mn1);
        m0 = mn0; m1 = mn1;

        float s0 = 0.f, s1 = 0.f;
        #pragma unroll
        for (int nt = 0; nt < 8; nt++) {
            sacc[nt][0] = __expf(sacc[nt][0] - mn0);
            sacc[nt][1] = __expf(sacc[nt][1] - mn0);
            sacc[nt][2] = __expf(sacc[nt][2] - mn1);
            sacc[nt][3] = __expf(sacc[nt][3] - mn1);
            s0 += sacc[nt][0] + sacc[nt][1];
            s1 += sacc[nt][2] + sacc[nt][3];
        }
        s0 += __shfl_xor_sync(0xffffffffu, s0, 1);
        s0 += __shfl_xor_sync(0xffffffffu, s0, 2);
        s1 += __shfl_xor_sync(0xffffffffu, s1, 1);
        s1 += __shfl_xor_sync(0xffffffffu, s1, 2);
        l0 = l0 * c0 + s0;
        l1 = l1 * c1 + s1;

        #pragma unroll
        for (int nt = 0; nt < 8; nt++) {
            oacc[nt][0] *= c0; oacc[nt][1] *= c0;
            oacc[nt][2] *= c1; oacc[nt][3] *= c1;
        }

        // ---- O += P V ----
        uint32_t pa[4][4];
        #pragma unroll
        for (int s = 0; s < 4; s++) {
            pa[s][0] = pack_h2(sacc[2*s][0],     sacc[2*s][1]);
            pa[s][1] = pack_h2(sacc[2*s][2],     sacc[2*s][3]);
            pa[s][2] = pack_h2(sacc[2*s + 1][0], sacc[2*s + 1][1]);
            pa[s][3] = pack_h2(sacc[2*s + 1][2], sacc[2*s + 1][3]);
        }
        #pragma unroll
        for (int nt2 = 0; nt2 < 8; nt2++) {
            #pragma unroll
            for (int sp = 0; sp < 2; sp++) {
                uint32_t vb[4];
                ldsm_x4(vb, VhS + (((nt2 * 8 + rr) * ASTW) + sp * 16 + q4 * 4) * 4);
                mma16816(oacc[nt2], pa[2 * sp],     &vb[0]);
                mma16816(oacc[nt2], pa[2 * sp + 1], &vb[2]);
            }
        }
    }

    // ---- finalize: write O as half hi ----
    float il0 = 1.0f / l0, il1 = 1.0f / l1;
    size_t row0 = (size_t)(b * T_ + q0 + wbase + g);
    uint32_t* ohw = (uint32_t*)g_oh;
    const int colw0 = (h * DH) >> 1;
    #pragma unroll
    for (int nt2 = 0; nt2 < 8; nt2++) {
        int w = colw0 + nt2 * 4 + t;
        ohw[row0 * 1024 + w]       = pack_h2(oacc[nt2][0] * il0, oacc[nt2][1] * il0);
        ohw[(row0 + 8) * 1024 + w] = pack_h2(oacc[nt2][2] * il1, oacc[nt2][3] * il1);
    }
}

// ---------------------------------------------------------------------------
// Launch: hidden_states, shared_k, shared_v, Wq, Wo -> out (float32 [B,T,Dm])
// ---------------------------------------------------------------------------
extern "C" void kernel_launch(void* const* d_in, const int* in_sizes, int n_in,
                              void* d_out, int out_size) {
    const float* hidden = (const float*)d_in[0];
    const float* Kin    = (const float*)d_in[1];
    const float* Vin    = (const float*)d_in[2];
    const float* Wq     = (const float*)d_in[3];
    const float* Wo     = (const float*)d_in[4];
    float* out          = (float*)d_out;

    cudaFuncSetAttribute(gemm_h_kernel<0>,
                         cudaFuncAttributeMaxDynamicSharedMemorySize, SMEM_G_BYTES);
    cudaFuncSetAttribute(gemm_h_kernel<1>,
                         cudaFuncAttributeMaxDynamicSharedMemorySize, SMEM_G_BYTES);
    cudaFuncSetAttribute(attn_mma_kernel,
                         cudaFuncAttributeMaxDynamicSharedMemorySize, SMEM_A_BYTES);

    rope_table_kernel<<<(T_ * (DH/2) + 255) / 256, 256>>>();
    split_f32_kernel<0><<<M_ * DM / 1024, 256>>>(hidden);
    split_f32_kernel<1><<<DM * DM / 1024, 256>>>(Wq);
    split_f32_kernel<2><<<DM * DM / 1024, 256>>>(Wo);
    prep_k_kernel<<<B_ * H_ * T_ * 16 / 256, 256>>>(Kin);
    prep_v_kernel<<<dim3(T_ / 64, H_, B_), 256>>>(Vin);

    dim3 gGemm(DM / 128, M_ / 128);   // (16, 32)
    gemm_h_kernel<0><<<gGemm, 256, SMEM_G_BYTES>>>(nullptr);

    dim3 gAttn(T_ / 128, H_, B_);     // (16, 32, 2)
    attn_mma_kernel<<<gAttn, 256, SMEM_A_BYTES>>>();

    gemm_h_kernel<1><<<gGemm, 256, SMEM_G_BYTES>>>(out);
}

// round 15
// speedup vs baseline: 1.1304x; 1.1304x over previous
#include <cuda_runtime.h>
#include <cuda_fp16.h>
#include <math.h>
#include <stdint.h>

// Problem constants
#define B_  2
#define T_  2048
#define DM  2048
#define H_  32
#define DH  64
#define M_  (B_*T_)   // 4096

// ---------------------------------------------------------------------------
// Half scratch (device globals: allocation-free per harness rules)
// ---------------------------------------------------------------------------
__device__ __half g_ah[(size_t)M_*DM];                           // hidden hi
__device__ __half g_wqh[(size_t)DM*DM];                          // Wq hi
__device__ __half g_woh[(size_t)DM*DM];                          // Wo hi
__device__ __half g_qh[(size_t)B_*H_*T_*DH];                     // rope'd+scaled Q hi
__device__ __half g_kh[(size_t)B_*H_*T_*DH];                     // K hi [B,H,T,Dh]
__device__ __half g_vth[(size_t)B_*H_*T_*DH];                    // V^T hi [B,H,Dh,T]
__device__ __half g_oh[(size_t)M_*DM];                           // attention out hi
__device__ float g_cos[T_*(DH/2)];
__device__ float g_sin[T_*(DH/2)];

// ---------------------------------------------------------------------------
// helpers
// ---------------------------------------------------------------------------
__device__ __forceinline__ uint32_t pack_h2(float a, float b) {
    __half2 h = __floats2half2_rn(a, b);
    return *(uint32_t*)&h;
}
__device__ __forceinline__ void mma16816(float* d, const uint32_t* a, const uint32_t* b) {
    asm volatile(
        "mma.sync.aligned.m16n8k16.row.col.f32.f16.f16.f32 "
        "{%0,%1,%2,%3}, {%4,%5,%6,%7}, {%8,%9}, {%0,%1,%2,%3};"
        : "+f"(d[0]), "+f"(d[1]), "+f"(d[2]), "+f"(d[3])
        : "r"(a[0]), "r"(a[1]), "r"(a[2]), "r"(a[3]), "r"(b[0]), "r"(b[1]));
}
__device__ __forceinline__ void ldsm_x4(uint32_t* r, uint32_t addr) {
    asm volatile(
        "ldmatrix.sync.aligned.m8n8.x4.shared.b16 {%0,%1,%2,%3}, [%4];"
        : "=r"(r[0]), "=r"(r[1]), "=r"(r[2]), "=r"(r[3]) : "r"(addr));
}
__device__ __forceinline__ void cp_async16(uint32_t saddr, const void* gptr) {
    asm volatile("cp.async.cg.shared.global [%0], [%1], 16;"
                 :: "r"(saddr), "l"(gptr));
}
#define CP_COMMIT() asm volatile("cp.async.commit_group;" ::: "memory")
#define CP_WAIT0()  asm volatile("cp.async.wait_group 0;" ::: "memory")

// ---------------------------------------------------------------------------
// RoPE table
// ---------------------------------------------------------------------------
__global__ void rope_table_kernel() {
    int idx = blockIdx.x * blockDim.x + threadIdx.x;
    if (idx >= T_ * (DH/2)) return;
    int t = idx >> 5;
    int i = idx & 31;
    double inv = pow(10000.0, -((double)(2 * i)) / 64.0);
    double ang = (double)t * inv;
    g_cos[idx] = (float)cos(ang);
    g_sin[idx] = (float)sin(ang);
}

// ---------------------------------------------------------------------------
// fp32 -> half hi prep, vectorized (float4 -> uint2).  WHICH: 0=hidden,1=Wq,2=Wo
// ---------------------------------------------------------------------------
template<int WHICH>
__global__ void split_f32_kernel(const float* __restrict__ in) {
    size_t i = (size_t)blockIdx.x * 256 + threadIdx.x;
    float4 v = ((const float4*)in)[i];
    uint2* hw = (uint2*)(WHICH == 0 ? g_ah : WHICH == 1 ? g_wqh : g_woh);
    hw[i] = make_uint2(pack_h2(v.x, v.y), pack_h2(v.z, v.w));
}

// ---------------------------------------------------------------------------
// K prep: [B,T,H,Dh] fp32 -> [B,H,T,Dh] half (hi only), float4 -> uint2.
// ---------------------------------------------------------------------------
__global__ void prep_k_kernel(const float* __restrict__ Kg) {
    uint32_t w = blockIdx.x * 256 + threadIdx.x;     // < B*H*T*16
    int dh4 = w & 15;
    int tok = (w >> 4) & (T_ - 1);
    int h   = (w >> 15) & (H_ - 1);
    int b   = (int)(w >> 20);
    float4 v = ((const float4*)Kg)[(((size_t)(b * T_ + tok)) * H_ + h) * 16 + dh4];
    ((uint2*)g_kh)[(((size_t)(b * H_ + h)) * T_ + tok) * 16 + dh4] =
        make_uint2(pack_h2(v.x, v.y), pack_h2(v.z, v.w));
}

// ---------------------------------------------------------------------------
// V prep: [B,T,H,Dh] fp32 -> transposed [B,H,Dh,T] half (hi only).
// ---------------------------------------------------------------------------
__global__ void prep_v_kernel(const float* __restrict__ Vg) {
    __shared__ float stg[64 * 65];
    const int tid = threadIdx.x;
    const int kt  = blockIdx.x, h = blockIdx.y, b = blockIdx.z;
    const float* src = Vg + ((size_t)(b * T_ + kt * 64) * H_ + h) * DH;

    #pragma unroll
    for (int i = 0; i < 4; i++) {
        int chunk = i * 256 + tid;            // 64 rows x 16 float4
        int r = chunk >> 4, c4 = chunk & 15;
        float4 v = *(const float4*)(src + (size_t)r * (H_ * DH) + c4 * 4);
        float* d = stg + r * 65 + c4 * 4;
        d[0] = v.x; d[1] = v.y; d[2] = v.z; d[3] = v.w;
    }
    __syncthreads();

    const int kp = tid & 31, dhg = tid >> 5;
    #pragma unroll
    for (int i = 0; i < 8; i++) {
        int dh = dhg * 8 + i;
        float v0 = stg[(2 * kp)     * 65 + dh];
        float v1 = stg[(2 * kp + 1) * 65 + dh];
        size_t idx = ((size_t)(b * H_ + h) * DH + dh) * (T_ / 2) + kt * 32 + kp;
        ((uint32_t*)g_vth)[idx] = pack_h2(v0, v1);
    }
}

// ---------------------------------------------------------------------------
// Pure-FP16 GEMM with 2-stage cp.async (R13-proven): C = A @ W^T (hi x hi).
// ---------------------------------------------------------------------------
#define GSTW 28
#define GT_W (128*GSTW)                 // 3584 words
#define G_STAGE_W (2*GT_W)              // 7168 words
#define SMEM_G_BYTES (2*G_STAGE_W*4)    // 57344 B

template<int MODE>
__global__ __launch_bounds__(256)
void gemm_h_kernel(float* __restrict__ C) {
    extern __shared__ uint32_t smw[];

    const uint4* Agh = (const uint4*)(MODE == 0 ? g_ah  : g_oh);
    const uint4* Bgh = (const uint4*)(MODE == 0 ? g_wqh : g_woh);

    const int tid   = threadIdx.x;
    const int wid   = tid >> 5;
    const int lane  = tid & 31;
    const int g     = lane >> 2;
    const int t     = lane & 3;
    const int warpR = wid >> 2;
    const int warpC = wid & 3;
    const int rowBase = blockIdx.y * 128;
    const int colBase = blockIdx.x * 128;

    const int q4 = lane >> 3;
    const int rr = lane & 7;
    const int arow = (q4 & 1) * 8 + rr;
    const int aoff = (q4 >> 1) * 4;
    const int brow = (q4 >> 1) * 8 + rr;
    const int boff = (q4 & 1) * 4;

    const uint32_t smemS = (uint32_t)__cvta_generic_to_shared(smw);

    const int lr2 = tid >> 2;   // 0..63
    const int lc2 = tid & 3;    // 0..3

    auto issue = [&](int st, int kt) {
        uint32_t base = smemS + (uint32_t)st * G_STAGE_W * 4;
        #pragma unroll
        for (int i = 0; i < 2; i++) {
            int r = lr2 + i * 64;
            uint32_t so = (uint32_t)(r * GSTW + lc2 * 4) * 4;
            size_t ai = ((size_t)(rowBase + r)) * 256 + kt * 4 + lc2;
            size_t bi = ((size_t)(colBase + r)) * 256 + kt * 4 + lc2;
            cp_async16(base + so,            Agh + ai);
            cp_async16(base + GT_W * 4 + so, Bgh + bi);
        }
    };

    float acc[4][4][4];
    #pragma unroll
    for (int mt = 0; mt < 4; mt++)
        #pragma unroll
        for (int nt = 0; nt < 4; nt++)
            #pragma unroll
            for (int i = 0; i < 4; i++) acc[mt][nt][i] = 0.f;

    issue(0, 0);
    CP_COMMIT();

    for (int kt = 0; kt < 64; kt++) {
        CP_WAIT0();
        __syncthreads();
        if (kt + 1 < 64) { issue((kt + 1) & 1, kt + 1); CP_COMMIT(); }

        const uint32_t AhS = smemS + (uint32_t)(kt & 1) * G_STAGE_W * 4;
        const uint32_t BhS = AhS + GT_W * 4;

        #pragma unroll
        for (int ks = 0; ks < 2; ks++) {
            uint32_t ah[4][4], bh[2][4];
            #pragma unroll
            for (int mt = 0; mt < 4; mt++) {
                uint32_t ao = ((warpR * 64 + mt * 16 + arow) * GSTW + ks * 8 + aoff) * 4;
                ldsm_x4(ah[mt], AhS + ao);
            }
            #pragma unroll
            for (int p = 0; p < 2; p++) {
                uint32_t bo = ((warpC * 32 + p * 16 + brow) * GSTW + ks * 8 + boff) * 4;
                ldsm_x4(bh[p], BhS + bo);
            }
            #pragma unroll
            for (int mt = 0; mt < 4; mt++)
                #pragma unroll
                for (int nt = 0; nt < 4; nt++)
                    mma16816(acc[mt][nt], ah[mt], &bh[nt >> 1][(nt & 1) * 2]);
        }
    }

    #pragma unroll
    for (int mt = 0; mt < 4; mt++) {
        #pragma unroll
        for (int nt = 0; nt < 4; nt++) {
            int m0 = rowBase + warpR * 64 + mt * 16 + g;
            int n  = colBase + warpC * 32 + nt * 8 + 2 * t;
            if (MODE == 0) {
                int hh = n >> 6;
                int d  = n & 63;   // even
                #pragma unroll
                for (int half = 0; half < 2; half++) {
                    int m = m0 + half * 8;
                    float x1 = acc[mt][nt][half * 2];
                    float x2 = acc[mt][nt][half * 2 + 1];
                    int bb = m >> 11;
                    int tt = m & (T_ - 1);
                    float c = g_cos[tt * 32 + (d >> 1)];
                    float s = g_sin[tt * 32 + (d >> 1)];
                    float xr1 = (x1 * c - x2 * s) * 0.125f;
                    float xr2 = (x1 * s + x2 * c) * 0.125f;
                    size_t idx = ((size_t)(bb * H_ + hh) * T_ + tt) * 32 + (d >> 1);
                    ((uint32_t*)g_qh)[idx] = pack_h2(xr1, xr2);
                }
            } else {
                float2 v0 = make_float2(acc[mt][nt][0], acc[mt][nt][1]);
                float2 v1 = make_float2(acc[mt][nt][2], acc[mt][nt][3]);
                *(float2*)(C + (size_t)m0 * DM + n)       = v0;
                *(float2*)(C + (size_t)(m0 + 8) * DM + n) = v1;
            }
        }
    }
}

// ---------------------------------------------------------------------------
// FP16 flash attention: 1-pass S, 1-pass PV, 2-stage cp.async.
// Q-tile 64 rows, 128 threads (4 warps x 16 rows) -> higher occupancy,
// finer load balance, half the diagonal-tile waste.
// ---------------------------------------------------------------------------
#define ASTW 44
#define AT_W (64*ASTW)                  // 2816 words / buffer
#define A_STAGE_W (2*AT_W)              // K + V per stage
#define SMEM_A_BYTES (2*A_STAGE_W*4)    // 45056 B

__global__ __launch_bounds__(128)
void attn_mma_kernel() {
    extern __shared__ uint32_t smw[];

    const int tid  = threadIdx.x;
    const int wid  = tid >> 5;          // 0..3
    const int lane = tid & 31;
    const int g    = lane >> 2;
    const int t    = lane & 3;
    const int bx   = (int)gridDim.x - 1 - (int)blockIdx.x;   // heavy blocks first
    const int h    = blockIdx.y;
    const int b    = blockIdx.z;
    const int q0   = bx * 64;
    const int wbase = wid * 16;

    const int q4 = lane >> 3;
    const int rr = lane & 7;

    const uint32_t smemS = (uint32_t)__cvta_generic_to_shared(smw);

    // ---- Q A-frags direct from gmem (hi only) ----
    uint32_t qh[4][4];
    {
        const uint32_t* qhw = (const uint32_t*)g_qh
            + (((size_t)(b * H_ + h)) * T_ + q0 + wbase + g) * 32;
        #pragma unroll
        for (int s = 0; s < 4; s++) {
            int o = s * 8 + t;
            qh[s][0] = qhw[o];           qh[s][1] = qhw[8 * 32 + o];
            qh[s][2] = qhw[o + 4];       qh[s][3] = qhw[8 * 32 + o + 4];
        }
    }

    float m0 = -1e30f, m1 = -1e30f, l0 = 0.f, l1 = 0.f;
    float oacc[8][4];
    #pragma unroll
    for (int nt = 0; nt < 8; nt++)
        #pragma unroll
        for (int i = 0; i < 4; i++) oacc[nt][i] = 0.f;

    const int nkt = bx + 1;

    const uint4* kh4 = (const uint4*)g_kh  + ((size_t)(b * H_ + h) * T_) * 8;
    const uint4* vh4 = (const uint4*)g_vth + ((size_t)(b * H_ + h) * DH) * (T_ / 8);

    const int ldr = tid >> 3;   // 0..15 (row, +16 per i)
    const int ldc = tid & 7;    // uint4 chunk

    // cp.async one 64-key K/V tile pair into stage st (128 threads, 4 rows each)
    auto issue = [&](int st, int kt) {
        uint32_t base = smemS + (uint32_t)st * A_STAGE_W * 4;
        #pragma unroll
        for (int i = 0; i < 4; i++) {
            int r = ldr + i * 16;
            uint32_t so = (uint32_t)(r * ASTW + ldc * 4) * 4;
            cp_async16(base + so,            kh4 + (size_t)(kt * 64 + r) * 8 + ldc);
            cp_async16(base + AT_W * 4 + so, vh4 + (size_t)r * 256 + kt * 8 + ldc);
        }
    };

    const int qw_min = q0 + wbase;
    const int qw_max = q0 + wbase + 15;

    issue(0, 0);
    CP_COMMIT();

    for (int kt = 0; kt < nkt; kt++) {
        const int ktb = kt * 64;

        CP_WAIT0();
        __syncthreads();
        if (kt + 1 < nkt) { issue((kt + 1) & 1, kt + 1); CP_COMMIT(); }

        if (ktb > qw_max) continue;   // fully masked for this warp

        const uint32_t KhS = smemS + (uint32_t)(kt & 1) * A_STAGE_W * 4;
        const uint32_t VhS = KhS + AT_W * 4;

        // ---- S = Q K^T (1-pass fp16) ----
        float sacc[8][4];
        #pragma unroll
        for (int nt = 0; nt < 8; nt++)
            #pragma unroll
            for (int i = 0; i < 4; i++) sacc[nt][i] = 0.f;

        #pragma unroll
        for (int nt = 0; nt < 8; nt++) {
            #pragma unroll
            for (int sp = 0; sp < 2; sp++) {
                uint32_t kb2[4];
                ldsm_x4(kb2, KhS + (((nt * 8 + rr) * ASTW) + sp * 16 + q4 * 4) * 4);
                mma16816(sacc[nt], qh[2 * sp],     &kb2[0]);
                mma16816(sacc[nt], qh[2 * sp + 1], &kb2[2]);
            }
        }

        // ---- causal mask (diagonal tiles only) ----
        if (ktb + 63 > qw_min) {
            int qr0 = qw_min + g, qr1 = qr0 + 8;
            #pragma unroll
            for (int nt = 0; nt < 8; nt++) {
                int kc0 = ktb + nt * 8 + 2 * t;
                if (kc0     > qr0) sacc[nt][0] = -1e30f;
                if (kc0 + 1 > qr0) sacc[nt][1] = -1e30f;
                if (kc0     > qr1) sacc[nt][2] = -1e30f;
                if (kc0 + 1 > qr1) sacc[nt][3] = -1e30f;
            }
        }

        // ---- online softmax ----
        float mx0 = -1e30f, mx1 = -1e30f;
        #pragma unroll
        for (int nt = 0; nt < 8; nt++) {
            mx0 = fmaxf(mx0, fmaxf(sacc[nt][0], sacc[nt][1]));
            mx1 = fmaxf(mx1, fmaxf(sacc[nt][2], sacc[nt][3]));
        }
        mx0 = fmaxf(mx0, __shfl_xor_sync(0xffffffffu, mx0, 1));
        mx0 = fmaxf(mx0, __shfl_xor_sync(0xffffffffu, mx0, 2));
        mx1 = fmaxf(mx1, __shfl_xor_sync(0xffffffffu, mx1, 1));
        mx1 = fmaxf(mx1, __shfl_xor_sync(0xffffffffu, mx1, 2));

        float mn0 = fmaxf(m0, mx0), mn1 = fmaxf(m1, mx1);
        float c0 = __expf(m0 - mn0), c1 = __expf(m1 - mn1);
        m0 = mn0; m1 = mn1;

        float s0 = 0.f, s1 = 0.f;
        #pragma unroll
        for (int nt = 0; nt < 8; nt++) {
            sacc[nt][0] = __expf(sacc[nt][0] - mn0);
            sacc[nt][1] = __expf(sacc[nt][1] - mn0);
            sacc[nt][2] = __expf(sacc[nt][2] - mn1);
            sacc[nt][3] = __expf(sacc[nt][3] - mn1);
            s0 += sacc[nt][0] + sacc[nt][1];
            s1 += sacc[nt][2] + sacc[nt][3];
        }
        s0 += __shfl_xor_sync(0xffffffffu, s0, 1);
        s0 += __shfl_xor_sync(0xffffffffu, s0, 2);
        s1 += __shfl_xor_sync(0xffffffffu, s1, 1);
        s1 += __shfl_xor_sync(0xffffffffu, s1, 2);
        l0 = l0 * c0 + s0;
        l1 = l1 * c1 + s1;

        #pragma unroll
        for (int nt = 0; nt < 8; nt++) {
            oacc[nt][0] *= c0; oacc[nt][1] *= c0;
            oacc[nt][2] *= c1; oacc[nt][3] *= c1;
        }

        // ---- O += P V ----
        uint32_t pa[4][4];
        #pragma unroll
        for (int s = 0; s < 4; s++) {
            pa[s][0] = pack_h2(sacc[2*s][0],     sacc[2*s][1]);
            pa[s][1] = pack_h2(sacc[2*s][2],     sacc[2*s][3]);
            pa[s][2] = pack_h2(sacc[2*s + 1][0], sacc[2*s + 1][1]);
            pa[s][3] = pack_h2(sacc[2*s + 1][2], sacc[2*s + 1][3]);
        }
        #pragma unroll
        for (int nt2 = 0; nt2 < 8; nt2++) {
            #pragma unroll
            for (int sp = 0; sp < 2; sp++) {
                uint32_t vb[4];
                ldsm_x4(vb, VhS + (((nt2 * 8 + rr) * ASTW) + sp * 16 + q4 * 4) * 4);
                mma16816(oacc[nt2], pa[2 * sp],     &vb[0]);
                mma16816(oacc[nt2], pa[2 * sp + 1], &vb[2]);
            }
        }
    }

    // ---- finalize: write O as half hi ----
    float il0 = 1.0f / l0, il1 = 1.0f / l1;
    size_t row0 = (size_t)(b * T_ + q0 + wbase + g);
    uint32_t* ohw = (uint32_t*)g_oh;
    const int colw0 = (h * DH) >> 1;
    #pragma unroll
    for (int nt2 = 0; nt2 < 8; nt2++) {
        int w = colw0 + nt2 * 4 + t;
        ohw[row0 * 1024 + w]       = pack_h2(oacc[nt2][0] * il0, oacc[nt2][1] * il0);
        ohw[(row0 + 8) * 1024 + w] = pack_h2(oacc[nt2][2] * il1, oacc[nt2][3] * il1);
    }
}

// ---------------------------------------------------------------------------
// Launch: hidden_states, shared_k, shared_v, Wq, Wo -> out (float32 [B,T,Dm])
// ---------------------------------------------------------------------------
extern "C" void kernel_launch(void* const* d_in, const int* in_sizes, int n_in,
                              void* d_out, int out_size) {
    const float* hidden = (const float*)d_in[0];
    const float* Kin    = (const float*)d_in[1];
    const float* Vin    = (const float*)d_in[2];
    const float* Wq     = (const float*)d_in[3];
    const float* Wo     = (const float*)d_in[4];
    float* out          = (float*)d_out;

    cudaFuncSetAttribute(gemm_h_kernel<0>,
                         cudaFuncAttributeMaxDynamicSharedMemorySize, SMEM_G_BYTES);
    cudaFuncSetAttribute(gemm_h_kernel<1>,
                         cudaFuncAttributeMaxDynamicSharedMemorySize, SMEM_G_BYTES);
    cudaFuncSetAttribute(attn_mma_kernel,
                         cudaFuncAttributeMaxDynamicSharedMemorySize, SMEM_A_BYTES);

    rope_table_kernel<<<(T_ * (DH/2) + 255) / 256, 256>>>();
    split_f32_kernel<0><<<M_ * DM / 1024, 256>>>(hidden);
    split_f32_kernel<1><<<DM * DM / 1024, 256>>>(Wq);
    split_f32_kernel<2><<<DM * DM / 1024, 256>>>(Wo);
    prep_k_kernel<<<B_ * H_ * T_ * 16 / 256, 256>>>(Kin);
    prep_v_kernel<<<dim3(T_ / 64, H_, B_), 256>>>(Vin);

    dim3 gGemm(DM / 128, M_ / 128);   // (16, 32)
    gemm_h_kernel<0><<<gGemm, 256, SMEM_G_BYTES>>>(nullptr);

    dim3 gAttn(T_ / 64, H_, B_);      // (32, 32, 2)
    attn_mma_kernel<<<gAttn, 128, SMEM_A_BYTES>>>();

    gemm_h_kernel<1><<<gGemm, 256, SMEM_G_BYTES>>>(out);
}

// round 16
// speedup vs baseline: 1.1727x; 1.0374x over previous
#include <cuda_runtime.h>
#include <cuda_fp16.h>
#include <math.h>
#include <stdint.h>

// Problem constants
#define B_  2
#define T_  2048
#define DM  2048
#define H_  32
#define DH  64
#define M_  (B_*T_)   // 4096

// ---------------------------------------------------------------------------
// Half scratch (device globals: allocation-free per harness rules)
// ---------------------------------------------------------------------------
__device__ __half g_ah[(size_t)M_*DM];                           // hidden hi
__device__ __half g_wqh[(size_t)DM*DM];                          // Wq hi
__device__ __half g_woh[(size_t)DM*DM];                          // Wo hi
__device__ __half g_qh[(size_t)B_*H_*T_*DH];                     // rope'd+scaled Q hi
__device__ __half g_kh[(size_t)B_*H_*T_*DH];                     // K hi [B,H,T,Dh]
__device__ __half g_vth[(size_t)B_*H_*T_*DH];                    // V^T hi [B,H,Dh,T]
__device__ __half g_oh[(size_t)M_*DM];                           // attention out hi
__device__ float g_cos[T_*(DH/2)];
__device__ float g_sin[T_*(DH/2)];

// ---------------------------------------------------------------------------
// helpers
// ---------------------------------------------------------------------------
__device__ __forceinline__ uint32_t pack_h2(float a, float b) {
    __half2 h = __floats2half2_rn(a, b);
    return *(uint32_t*)&h;
}
__device__ __forceinline__ void mma16816(float* d, const uint32_t* a, const uint32_t* b) {
    asm volatile(
        "mma.sync.aligned.m16n8k16.row.col.f32.f16.f16.f32 "
        "{%0,%1,%2,%3}, {%4,%5,%6,%7}, {%8,%9}, {%0,%1,%2,%3};"
        : "+f"(d[0]), "+f"(d[1]), "+f"(d[2]), "+f"(d[3])
        : "r"(a[0]), "r"(a[1]), "r"(a[2]), "r"(a[3]), "r"(b[0]), "r"(b[1]));
}
__device__ __forceinline__ void ldsm_x4(uint32_t* r, uint32_t addr) {
    asm volatile(
        "ldmatrix.sync.aligned.m8n8.x4.shared.b16 {%0,%1,%2,%3}, [%4];"
        : "=r"(r[0]), "=r"(r[1]), "=r"(r[2]), "=r"(r[3]) : "r"(addr));
}
__device__ __forceinline__ void cp_async16(uint32_t saddr, const void* gptr) {
    asm volatile("cp.async.cg.shared.global [%0], [%1], 16;"
                 :: "r"(saddr), "l"(gptr));
}
#define CP_COMMIT() asm volatile("cp.async.commit_group;" ::: "memory")
#define CP_WAIT0()  asm volatile("cp.async.wait_group 0;" ::: "memory")

// ---------------------------------------------------------------------------
// RoPE table
// ---------------------------------------------------------------------------
__global__ void rope_table_kernel() {
    int idx = blockIdx.x * blockDim.x + threadIdx.x;
    if (idx >= T_ * (DH/2)) return;
    int t = idx >> 5;
    int i = idx & 31;
    double inv = pow(10000.0, -((double)(2 * i)) / 64.0);
    double ang = (double)t * inv;
    g_cos[idx] = (float)cos(ang);
    g_sin[idx] = (float)sin(ang);
}

// ---------------------------------------------------------------------------
// fp32 -> half hi prep, vectorized (float4 -> uint2).  WHICH: 0=hidden,1=Wq,2=Wo
// ---------------------------------------------------------------------------
template<int WHICH>
__global__ void split_f32_kernel(const float* __restrict__ in) {
    size_t i = (size_t)blockIdx.x * 256 + threadIdx.x;
    float4 v = ((const float4*)in)[i];
    uint2* hw = (uint2*)(WHICH == 0 ? g_ah : WHICH == 1 ? g_wqh : g_woh);
    hw[i] = make_uint2(pack_h2(v.x, v.y), pack_h2(v.z, v.w));
}

// ---------------------------------------------------------------------------
// K prep: [B,T,H,Dh] fp32 -> [B,H,T,Dh] half (hi only), float4 -> uint2.
// ---------------------------------------------------------------------------
__global__ void prep_k_kernel(const float* __restrict__ Kg) {
    uint32_t w = blockIdx.x * 256 + threadIdx.x;     // < B*H*T*16
    int dh4 = w & 15;
    int tok = (w >> 4) & (T_ - 1);
    int h   = (w >> 15) & (H_ - 1);
    int b   = (int)(w >> 20);
    float4 v = ((const float4*)Kg)[(((size_t)(b * T_ + tok)) * H_ + h) * 16 + dh4];
    ((uint2*)g_kh)[(((size_t)(b * H_ + h)) * T_ + tok) * 16 + dh4] =
        make_uint2(pack_h2(v.x, v.y), pack_h2(v.z, v.w));
}

// ---------------------------------------------------------------------------
// V prep: [B,T,H,Dh] fp32 -> transposed [B,H,Dh,T] half (hi only).
// ---------------------------------------------------------------------------
__global__ void prep_v_kernel(const float* __restrict__ Vg) {
    __shared__ float stg[64 * 65];
    const int tid = threadIdx.x;
    const int kt  = blockIdx.x, h = blockIdx.y, b = blockIdx.z;
    const float* src = Vg + ((size_t)(b * T_ + kt * 64) * H_ + h) * DH;

    #pragma unroll
    for (int i = 0; i < 4; i++) {
        int chunk = i * 256 + tid;            // 64 rows x 16 float4
        int r = chunk >> 4, c4 = chunk & 15;
        float4 v = *(const float4*)(src + (size_t)r * (H_ * DH) + c4 * 4);
        float* d = stg + r * 65 + c4 * 4;
        d[0] = v.x; d[1] = v.y; d[2] = v.z; d[3] = v.w;
    }
    __syncthreads();

    const int kp = tid & 31, dhg = tid >> 5;
    #pragma unroll
    for (int i = 0; i < 8; i++) {
        int dh = dhg * 8 + i;
        float v0 = stg[(2 * kp)     * 65 + dh];
        float v1 = stg[(2 * kp + 1) * 65 + dh];
        size_t idx = ((size_t)(b * H_ + h) * DH + dh) * (T_ / 2) + kt * 32 + kp;
        ((uint32_t*)g_vth)[idx] = pack_h2(v0, v1);
    }
}

// ---------------------------------------------------------------------------
// Pure-FP16 GEMM, 2-stage cp.async, BK=64 per stage (wide sync window).
// C = A @ W^T (hi x hi). CTA 128x128, 256 threads.
// Row = 64 k-values = 32 words data + 4 pad = stride 36 (conflict-free ldsm).
// ---------------------------------------------------------------------------
#define GSTW 36
#define GT_W (128*GSTW)                 // 4608 words per operand tile
#define G_STAGE_W (2*GT_W)              // 9216 words
#define SMEM_G_BYTES (2*G_STAGE_W*4)    // 73728 B

template<int MODE>
__global__ __launch_bounds__(256)
void gemm_h_kernel(float* __restrict__ C) {
    extern __shared__ uint32_t smw[];

    const uint4* Agh = (const uint4*)(MODE == 0 ? g_ah  : g_oh);
    const uint4* Bgh = (const uint4*)(MODE == 0 ? g_wqh : g_woh);

    const int tid   = threadIdx.x;
    const int wid   = tid >> 5;
    const int lane  = tid & 31;
    const int g     = lane >> 2;
    const int t     = lane & 3;
    const int warpR = wid >> 2;
    const int warpC = wid & 3;
    const int rowBase = blockIdx.y * 128;
    const int colBase = blockIdx.x * 128;

    const int q4 = lane >> 3;
    const int rr = lane & 7;
    const int arow = (q4 & 1) * 8 + rr;
    const int aoff = (q4 >> 1) * 4;
    const int brow = (q4 >> 1) * 8 + rr;
    const int boff = (q4 & 1) * 4;

    const uint32_t smemS = (uint32_t)__cvta_generic_to_shared(smw);

    const int ldr = tid >> 3;   // 0..31 (row base, +32 per i)
    const int ldc = tid & 7;    // uint4 chunk within 32-word row

    // cp.async one BK=64 tile pair into stage st (4 chunks per operand/thread)
    auto issue = [&](int st, int kt2) {
        uint32_t base = smemS + (uint32_t)st * G_STAGE_W * 4;
        #pragma unroll
        for (int i = 0; i < 4; i++) {
            int r = ldr + i * 32;
            uint32_t so = (uint32_t)(r * GSTW + ldc * 4) * 4;
            size_t ai = ((size_t)(rowBase + r)) * 256 + kt2 * 8 + ldc;
            size_t bi = ((size_t)(colBase + r)) * 256 + kt2 * 8 + ldc;
            cp_async16(base + so,            Agh + ai);
            cp_async16(base + GT_W * 4 + so, Bgh + bi);
        }
    };

    float acc[4][4][4];
    #pragma unroll
    for (int mt = 0; mt < 4; mt++)
        #pragma unroll
        for (int nt = 0; nt < 4; nt++)
            #pragma unroll
            for (int i = 0; i < 4; i++) acc[mt][nt][i] = 0.f;

    issue(0, 0);
    CP_COMMIT();

    for (int kt2 = 0; kt2 < 32; kt2++) {
        CP_WAIT0();
        __syncthreads();
        if (kt2 + 1 < 32) { issue((kt2 + 1) & 1, kt2 + 1); CP_COMMIT(); }

        const uint32_t AhS = smemS + (uint32_t)(kt2 & 1) * G_STAGE_W * 4;
        const uint32_t BhS = AhS + GT_W * 4;

        #pragma unroll
        for (int ks = 0; ks < 4; ks++) {
            uint32_t ah[4][4], bh[2][4];
            #pragma unroll
            for (int mt = 0; mt < 4; mt++) {
                uint32_t ao = ((warpR * 64 + mt * 16 + arow) * GSTW + ks * 8 + aoff) * 4;
                ldsm_x4(ah[mt], AhS + ao);
            }
            #pragma unroll
            for (int p = 0; p < 2; p++) {
                uint32_t bo = ((warpC * 32 + p * 16 + brow) * GSTW + ks * 8 + boff) * 4;
                ldsm_x4(bh[p], BhS + bo);
            }
            #pragma unroll
            for (int mt = 0; mt < 4; mt++)
                #pragma unroll
                for (int nt = 0; nt < 4; nt++)
                    mma16816(acc[mt][nt], ah[mt], &bh[nt >> 1][(nt & 1) * 2]);
        }
    }

    #pragma unroll
    for (int mt = 0; mt < 4; mt++) {
        #pragma unroll
        for (int nt = 0; nt < 4; nt++) {
            int m0 = rowBase + warpR * 64 + mt * 16 + g;
            int n  = colBase + warpC * 32 + nt * 8 + 2 * t;
            if (MODE == 0) {
                int hh = n >> 6;
                int d  = n & 63;   // even
                #pragma unroll
                for (int half = 0; half < 2; half++) {
                    int m = m0 + half * 8;
                    float x1 = acc[mt][nt][half * 2];
                    float x2 = acc[mt][nt][half * 2 + 1];
                    int bb = m >> 11;
                    int tt = m & (T_ - 1);
                    float c = g_cos[tt * 32 + (d >> 1)];
                    float s = g_sin[tt * 32 + (d >> 1)];
                    float xr1 = (x1 * c - x2 * s) * 0.125f;
                    float xr2 = (x1 * s + x2 * c) * 0.125f;
                    size_t idx = ((size_t)(bb * H_ + hh) * T_ + tt) * 32 + (d >> 1);
                    ((uint32_t*)g_qh)[idx] = pack_h2(xr1, xr2);
                }
            } else {
                float2 v0 = make_float2(acc[mt][nt][0], acc[mt][nt][1]);
                float2 v1 = make_float2(acc[mt][nt][2], acc[mt][nt][3]);
                *(float2*)(C + (size_t)m0 * DM + n)       = v0;
                *(float2*)(C + (size_t)(m0 + 8) * DM + n) = v1;
            }
        }
    }
}

// ---------------------------------------------------------------------------
// FP16 flash attention: 1-pass S, 1-pass PV, 2-stage cp.async (R15-proven).
// Q-tile 64 rows, 128 threads (4 warps x 16 rows).
// ---------------------------------------------------------------------------
#define ASTW 44
#define AT_W (64*ASTW)                  // 2816 words / buffer
#define A_STAGE_W (2*AT_W)              // K + V per stage
#define SMEM_A_BYTES (2*A_STAGE_W*4)    // 45056 B

__global__ __launch_bounds__(128)
void attn_mma_kernel() {
    extern __shared__ uint32_t smw[];

    const int tid  = threadIdx.x;
    const int wid  = tid >> 5;          // 0..3
    const int lane = tid & 31;
    const int g    = lane >> 2;
    const int t    = lane & 3;
    const int bx   = (int)gridDim.x - 1 - (int)blockIdx.x;   // heavy blocks first
    const int h    = blockIdx.y;
    const int b    = blockIdx.z;
    const int q0   = bx * 64;
    const int wbase = wid * 16;

    const int q4 = lane >> 3;
    const int rr = lane & 7;

    const uint32_t smemS = (uint32_t)__cvta_generic_to_shared(smw);

    // ---- Q A-frags direct from gmem (hi only) ----
    uint32_t qh[4][4];
    {
        const uint32_t* qhw = (const uint32_t*)g_qh
            + (((size_t)(b * H_ + h)) * T_ + q0 + wbase + g) * 32;
        #pragma unroll
        for (int s = 0; s < 4; s++) {
            int o = s * 8 + t;
            qh[s][0] = qhw[o];           qh[s][1] = qhw[8 * 32 + o];
            qh[s][2] = qhw[o + 4];       qh[s][3] = qhw[8 * 32 + o + 4];
        }
    }

    float m0 = -1e30f, m1 = -1e30f, l0 = 0.f, l1 = 0.f;
    float oacc[8][4];
    #pragma unroll
    for (int nt = 0; nt < 8; nt++)
        #pragma unroll
        for (int i = 0; i < 4; i++) oacc[nt][i] = 0.f;

    const int nkt = bx + 1;

    const uint4* kh4 = (const uint4*)g_kh  + ((size_t)(b * H_ + h) * T_) * 8;
    const uint4* vh4 = (const uint4*)g_vth + ((size_t)(b * H_ + h) * DH) * (T_ / 8);

    const int ldr = tid >> 3;   // 0..15 (row, +16 per i)
    const int ldc = tid & 7;    // uint4 chunk

    auto issue = [&](int st, int kt) {
        uint32_t base = smemS + (uint32_t)st * A_STAGE_W * 4;
        #pragma unroll
        for (int i = 0; i < 4; i++) {
            int r = ldr + i * 16;
            uint32_t so = (uint32_t)(r * ASTW + ldc * 4) * 4;
            cp_async16(base + so,            kh4 + (size_t)(kt * 64 + r) * 8 + ldc);
            cp_async16(base + AT_W * 4 + so, vh4 + (size_t)r * 256 + kt * 8 + ldc);
        }
    };

    const int qw_min = q0 + wbase;
    const int qw_max = q0 + wbase + 15;

    issue(0, 0);
    CP_COMMIT();

    for (int kt = 0; kt < nkt; kt++) {
        const int ktb = kt * 64;

        CP_WAIT0();
        __syncthreads();
        if (kt + 1 < nkt) { issue((kt + 1) & 1, kt + 1); CP_COMMIT(); }

        if (ktb > qw_max) continue;   // fully masked for this warp

        const uint32_t KhS = smemS + (uint32_t)(kt & 1) * A_STAGE_W * 4;
        const uint32_t VhS = KhS + AT_W * 4;

        // ---- S = Q K^T (1-pass fp16) ----
        float sacc[8][4];
        #pragma unroll
        for (int nt = 0; nt < 8; nt++)
            #pragma unroll
            for (int i = 0; i < 4; i++) sacc[nt][i] = 0.f;

        #pragma unroll
        for (int nt = 0; nt < 8; nt++) {
            #pragma unroll
            for (int sp = 0; sp < 2; sp++) {
                uint32_t kb2[4];
                ldsm_x4(kb2, KhS + (((nt * 8 + rr) * ASTW) + sp * 16 + q4 * 4) * 4);
                mma16816(sacc[nt], qh[2 * sp],     &kb2[0]);
                mma16816(sacc[nt], qh[2 * sp + 1], &kb2[2]);
            }
        }

        // ---- causal mask (diagonal tiles only) ----
        if (ktb + 63 > qw_min) {
            int qr0 = qw_min + g, qr1 = qr0 + 8;
            #pragma unroll
            for (int nt = 0; nt < 8; nt++) {
                int kc0 = ktb + nt * 8 + 2 * t;
                if (kc0     > qr0) sacc[nt][0] = -1e30f;
                if (kc0 + 1 > qr0) sacc[nt][1] = -1e30f;
                if (kc0     > qr1) sacc[nt][2] = -1e30f;
                if (kc0 + 1 > qr1) sacc[nt][3] = -1e30f;
            }
        }

        // ---- online softmax ----
        float mx0 = -1e30f, mx1 = -1e30f;
        #pragma unroll
        for (int nt = 0; nt < 8; nt++) {
            mx0 = fmaxf(mx0, fmaxf(sacc[nt][0], sacc[nt][1]));
            mx1 = fmaxf(mx1, fmaxf(sacc[nt][2], sacc[nt][3]));
        }
        mx0 = fmaxf(mx0, __shfl_xor_sync(0xffffffffu, mx0, 1));
        mx0 = fmaxf(mx0, __shfl_xor_sync(0xffffffffu, mx0, 2));
        mx1 = fmaxf(mx1, __shfl_xor_sync(0xffffffffu, mx1, 1));
        mx1 = fmaxf(mx1, __shfl_xor_sync(0xffffffffu, mx1, 2));

        float mn0 = fmaxf(m0, mx0), mn1 = fmaxf(m1, mx1);
        float c0 = __expf(m0 - mn0), c1 = __expf(m1 - mn1);
        m0 = mn0; m1 = mn1;

        float s0 = 0.f, s1 = 0.f;
        #pragma unroll
        for (int nt = 0; nt < 8; nt++) {
            sacc[nt][0] = __expf(sacc[nt][0] - mn0);
            sacc[nt][1] = __expf(sacc[nt][1] - mn0);
            sacc[nt][2] = __expf(sacc[nt][2] - mn1);
            sacc[nt][3] = __expf(sacc[nt][3] - mn1);
            s0 += sacc[nt][0] + sacc[nt][1];
            s1 += sacc[nt][2] + sacc[nt][3];
        }
        s0 += __shfl_xor_sync(0xffffffffu, s0, 1);
        s0 += __shfl_xor_sync(0xffffffffu, s0, 2);
        s1 += __shfl_xor_sync(0xffffffffu, s1, 1);
        s1 += __shfl_xor_sync(0xffffffffu, s1, 2);
        l0 = l0 * c0 + s0;
        l1 = l1 * c1 + s1;

        #pragma unroll
        for (int nt = 0; nt < 8; nt++) {
            oacc[nt][0] *= c0; oacc[nt][1] *= c0;
            oacc[nt][2] *= c1; oacc[nt][3] *= c1;
        }

        // ---- O += P V ----
        uint32_t pa[4][4];
        #pragma unroll
        for (int s = 0; s < 4; s++) {
            pa[s][0] = pack_h2(sacc[2*s][0],     sacc[2*s][1]);
            pa[s][1] = pack_h2(sacc[2*s][2],     sacc[2*s][3]);
            pa[s][2] = pack_h2(sacc[2*s + 1][0], sacc[2*s + 1][1]);
            pa[s][3] = pack_h2(sacc[2*s + 1][2], sacc[2*s + 1][3]);
        }
        #pragma unroll
        for (int nt2 = 0; nt2 < 8; nt2++) {
            #pragma unroll
            for (int sp = 0; sp < 2; sp++) {
                uint32_t vb[4];
                ldsm_x4(vb, VhS + (((nt2 * 8 + rr) * ASTW) + sp * 16 + q4 * 4) * 4);
                mma16816(oacc[nt2], pa[2 * sp],     &vb[0]);
                mma16816(oacc[nt2], pa[2 * sp + 1], &vb[2]);
            }
        }
    }

    // ---- finalize: write O as half hi ----
    float il0 = 1.0f / l0, il1 = 1.0f / l1;
    size_t row0 = (size_t)(b * T_ + q0 + wbase + g);
    uint32_t* ohw = (uint32_t*)g_oh;
    const int colw0 = (h * DH) >> 1;
    #pragma unroll
    for (int nt2 = 0; nt2 < 8; nt2++) {
        int w = colw0 + nt2 * 4 + t;
        ohw[row0 * 1024 + w]       = pack_h2(oacc[nt2][0] * il0, oacc[nt2][1] * il0);
        ohw[(row0 + 8) * 1024 + w] = pack_h2(oacc[nt2][2] * il1, oacc[nt2][3] * il1);
    }
}

// ---------------------------------------------------------------------------
// Launch: hidden_states, shared_k, shared_v, Wq, Wo -> out (float32 [B,T,Dm])
// ---------------------------------------------------------------------------
extern "C" void kernel_launch(void* const* d_in, const int* in_sizes, int n_in,
                              void* d_out, int out_size) {
    const float* hidden = (const float*)d_in[0];
    const float* Kin    = (const float*)d_in[1];
    const float* Vin    = (const float*)d_in[2];
    const float* Wq     = (const float*)d_in[3];
    const float* Wo     = (const float*)d_in[4];
    float* out          = (float*)d_out;

    cudaFuncSetAttribute(gemm_h_kernel<0>,
                         cudaFuncAttributeMaxDynamicSharedMemorySize, SMEM_G_BYTES);
    cudaFuncSetAttribute(gemm_h_kernel<1>,
                         cudaFuncAttributeMaxDynamicSharedMemorySize, SMEM_G_BYTES);
    cudaFuncSetAttribute(attn_mma_kernel,
                         cudaFuncAttributeMaxDynamicSharedMemorySize, SMEM_A_BYTES);

    rope_table_kernel<<<(T_ * (DH/2) + 255) / 256, 256>>>();
    split_f32_kernel<0><<<M_ * DM / 1024, 256>>>(hidden);
    split_f32_kernel<1><<<DM * DM / 1024, 256>>>(Wq);
    split_f32_kernel<2><<<DM * DM / 1024, 256>>>(Wo);
    prep_k_kernel<<<B_ * H_ * T_ * 16 / 256, 256>>>(Kin);
    prep_v_kernel<<<dim3(T_ / 64, H_, B_), 256>>>(Vin);

    dim3 gGemm(DM / 128, M_ / 128);   // (16, 32)
    gemm_h_kernel<0><<<gGemm, 256, SMEM_G_BYTES>>>(nullptr);

    dim3 gAttn(T_ / 64, H_, B_);      // (32, 32, 2)
    attn_mma_kernel<<<gAttn, 128, SMEM_A_BYTES>>>();

    gemm_h_kernel<1><<<gGemm, 256, SMEM_G_BYTES>>>(out);
}